// round 1
// baseline (speedup 1.0000x reference)
#include <cuda_runtime.h>

#define SNE_H 1080
#define SNE_W 1920
#define SNE_HW (SNE_H * SNE_W)

// Bit-pattern NaN test — immune to any fast-math flag the harness may use.
__device__ __forceinline__ bool f_isnan(float x) {
    return (__float_as_uint(x) & 0x7fffffffu) > 0x7f800000u;
}

__global__ void __launch_bounds__(256)
sne_kernel(const float* __restrict__ depth,
           const float* __restrict__ cam,
           float* __restrict__ out)
{
    const int u = blockIdx.x * 32 + threadIdx.x;
    const int v = blockIdx.y * 8  + threadIdx.y;
    if (u >= SNE_W || v >= SNE_H) return;

    const float fx = cam[0], cx = cam[2], fy = cam[4], cy = cam[5];
    const float inv_fx = __frcp_rn(fx);

    // 3x3 neighborhood: X, Y, Z (masked), and D = 1/Z for the 4 cross neighbors.
    // Out-of-bounds => 0 for everything (zero 'SAME' padding of the conv inputs).
    float xs[9], ys[9], zs[9], ds[9];
#pragma unroll
    for (int k = 0; k < 9; ++k) {
        const int dv = k / 3 - 1, du = k % 3 - 1;
        const int vv = v + dv, uu = u + du;
        float x = 0.f, y = 0.f, z = 0.f, d = 0.f;
        if (vv >= 0 && vv < SNE_H && uu >= 0 && uu < SNE_W) {
            const float z0 = __ldg(depth + vv * SNE_W + uu);
            y = z0 * ((float)vv - cy) * inv_fx;
            const bool neg = (y <= 0.f);
            z = neg ? 0.f : z0;
            y = neg ? 0.f : y;
            x = z0 * ((float)uu - cx) * inv_fx;
            d = __frcp_rn(z);   // +inf where z == 0, matching jnp 1/Z semantics
        }
        xs[k] = x; ys[k] = y; zs[k] = z; ds[k] = d;
    }

    // Gx/Gy central differences of D (zero padded), scaled by fx/fy.
    const float nxt = fx * (ds[5] - ds[3]);
    const float nyt = fy * (ds[7] - ds[1]);

    // phi = atan(ny_t/nx_t) + PI.  __fdividef gives correct inf/NaN propagation:
    // x/0 -> inf, 0/0 -> NaN, inf/inf -> NaN.
    const float phi = atanf(__fdividef(nyt, nxt)) + 3.14159265358979f;
    const float a = cosf(phi);
    const float b = sinf(phi);

    // 8 directional differences; NaN-masked accumulation of normalized components.
    float snx = 0.f, sny = 0.f, snz = 0.f;
#pragma unroll
    for (int k = 0; k < 9; ++k) {
        if (k == 4) continue;
        const float Xd  = xs[4] - xs[k];
        const float Yd  = ys[4] - ys[k];
        const float Zd  = zs[4] - zs[k];
        const float nzi = __fdividef(nxt * Xd + nyt * Yd, Zd);
        // 1/norm via rsqrt: rsqrt(inf)=0 so finite/inf -> 0 and inf/inf -> NaN,
        // both matching the reference's division-by-norm semantics after masking.
        const float rn  = rsqrtf(nxt * nxt + nyt * nyt + nzi * nzi);
        const float c1 = nxt * rn;
        const float c2 = nyt * rn;
        const float c3 = nzi * rn;
        snx += f_isnan(c1) ? 0.f : c1;
        sny += f_isnan(c2) ? 0.f : c2;
        snz += f_isnan(c3) ? 0.f : c3;
    }

    const float theta = -atanf(__fdividef(snx * a + sny * b, snz));
    const float st = sinf(theta);
    float nx = st * a;
    float ny = st * b;
    float nz = cosf(theta);

    const bool bad = f_isnan(nz);
    nx = bad ? 0.f : nx;
    ny = bad ? 0.f : ny;
    nz = bad ? -1.f : nz;
    const float sgn = (ny > 0.f) ? -1.f : 1.f;

    const int idx = v * SNE_W + u;
    out[idx]              = nx * sgn;
    out[SNE_HW + idx]     = ny * sgn;
    out[2 * SNE_HW + idx] = nz * sgn;
}

extern "C" void kernel_launch(void* const* d_in, const int* in_sizes, int n_in,
                              void* d_out, int out_size) {
    const float* depth = (const float*)d_in[0];
    const float* cam   = (const float*)d_in[1];
    float* out = (float*)d_out;
    dim3 blk(32, 8);
    dim3 grd((SNE_W + 31) / 32, (SNE_H + 7) / 8);
    sne_kernel<<<grd, blk>>>(depth, cam, out);
}

// round 2
// speedup vs baseline: 1.4724x; 1.4724x over previous
#include <cuda_runtime.h>

#define SNE_H 1080
#define SNE_W 1920
#define SNE_HW (SNE_H * SNE_W)
#define BX 32
#define BY 16
#define TX (BX + 2)   // 34
#define TY (BY + 2)   // 18

// Bit-pattern NaN test — immune to fast-math folding.
__device__ __forceinline__ bool f_isnan(float x) {
    return (__float_as_uint(x) & 0x7fffffffu) > 0x7f800000u;
}

__global__ void __launch_bounds__(BX * BY, 2)
sne_kernel(const float* __restrict__ depth,
           const float* __restrict__ cam,
           float* __restrict__ out)
{
    __shared__ float4 tile[TY][TX];   // (X, Y, Z_masked, D=1/Z) per pixel

    const int tx = threadIdx.x, ty = threadIdx.y;
    const int tid = ty * BX + tx;
    const int bu = blockIdx.x * BX, bv = blockIdx.y * BY;

    const float fx = cam[0], cx = cam[2], fy = cam[4], cy = cam[5];
    const float inv_fx = __frcp_rn(fx);

    // ---- Fill halo tile: compute X/Y/Z/D exactly once per pixel ----
    for (int i = tid; i < TX * TY; i += BX * BY) {
        const int lv = i / TX, lu = i - lv * TX;
        const int vv = bv + lv - 1, uu = bu + lu - 1;
        float4 t = make_float4(0.f, 0.f, 0.f, 0.f);   // zero 'SAME' padding
        if ((unsigned)vv < SNE_H && (unsigned)uu < SNE_W) {
            const float z0 = __ldg(depth + vv * SNE_W + uu);
            float y = z0 * ((float)vv - cy) * inv_fx;
            const bool neg = (y <= 0.f);
            const float z = neg ? 0.f : z0;
            y = neg ? 0.f : y;
            const float x = z0 * ((float)uu - cx) * inv_fx;  // X is NOT masked (matches ref)
            const float d = __frcp_rn(z);                    // +inf where z == 0
            t = make_float4(x, y, z, d);
        }
        tile[lv][lu] = t;
    }
    __syncthreads();

    const int u = bu + tx, v = bv + ty;
    if (v >= SNE_H) return;   // u always < W (1920 % 32 == 0)

    // ---- 3x3 neighborhood from shared memory ----
    const float4 c   = tile[ty + 1][tx + 1];
    const float4 n00 = tile[ty    ][tx    ];
    const float4 n01 = tile[ty    ][tx + 1];
    const float4 n02 = tile[ty    ][tx + 2];
    const float4 n10 = tile[ty + 1][tx    ];
    const float4 n12 = tile[ty + 1][tx + 2];
    const float4 n20 = tile[ty + 2][tx    ];
    const float4 n21 = tile[ty + 2][tx + 1];
    const float4 n22 = tile[ty + 2][tx + 2];

    // Gx/Gy central differences of D, scaled.
    const float nxt = fx * (n12.w - n10.w);
    const float nyt = fy * (n21.w - n01.w);

    // phi = atan(nyt/nxt) + PI; use cos(phi) = -1/sqrt(1+t^2), sin(phi) = -t/sqrt(1+t^2).
    // Clamp |t| at 1e18 so t = +/-inf (and t^2 overflow) gives b ~= -sign(t),
    // matching sinf(pi +/- pi/2) ~= -/+1. NaN t falls through the ordered compare.
    const float t = __fdividef(nyt, nxt);
    float at = fabsf(t);
    at = (at > 1e18f) ? 1e18f : at;              // NaN stays NaN
    const float rp = rsqrtf(fmaf(at, at, 1.f));
    const float a = -rp;                         // cos(phi)
    const float b = -copysignf(at * rp, t);      // sin(phi)

    // ---- 8 directional differences, NaN-masked normalized accumulation ----
    const float nn = fmaf(nxt, nxt, nyt * nyt);
    float snx = 0.f, sny = 0.f, snz = 0.f;
    const float4 nb[8] = { n00, n01, n02, n10, n12, n20, n21, n22 };
#pragma unroll
    for (int k = 0; k < 8; ++k) {
        const float Xd = c.x - nb[k].x;
        const float Yd = c.y - nb[k].y;
        const float Zd = c.z - nb[k].z;
        const float nzi = __fdividef(fmaf(nxt, Xd, nyt * Yd), Zd);
        const float rn  = rsqrtf(fmaf(nzi, nzi, nn));
        const float c1 = nxt * rn;
        const float c2 = nyt * rn;
        const float c3 = nzi * rn;
        if (!f_isnan(c1)) snx += c1;
        if (!f_isnan(c2)) sny += c2;
        if (!f_isnan(c3)) snz += c3;
    }

    // theta = -atan(s): sin(theta) = -s/sqrt(1+s^2), cos(theta) = 1/sqrt(1+s^2).
    const float s = __fdividef(fmaf(snx, a, sny * b), snz);
    float as_ = fabsf(s);
    as_ = (as_ > 1e18f) ? 1e18f : as_;           // NaN stays NaN
    const float rs = rsqrtf(fmaf(as_, as_, 1.f));
    const float st = -copysignf(as_ * rs, s);    // sin(theta)
    float nz = rs;                               // cos(theta); NaN iff s NaN
    float nx = st * a;
    float ny = st * b;

    const bool bad = f_isnan(nz);
    nx = bad ? 0.f : nx;
    ny = bad ? 0.f : ny;
    nz = bad ? -1.f : nz;
    const float sgn = (ny > 0.f) ? -1.f : 1.f;

    const int idx = v * SNE_W + u;
    out[idx]              = nx * sgn;
    out[SNE_HW + idx]     = ny * sgn;
    out[2 * SNE_HW + idx] = nz * sgn;
}

extern "C" void kernel_launch(void* const* d_in, const int* in_sizes, int n_in,
                              void* d_out, int out_size) {
    const float* depth = (const float*)d_in[0];
    const float* cam   = (const float*)d_in[1];
    float* out = (float*)d_out;
    dim3 blk(BX, BY);
    dim3 grd(SNE_W / BX, (SNE_H + BY - 1) / BY);
    sne_kernel<<<grd, blk>>>(depth, cam, out);
}